// round 15
// baseline (speedup 1.0000x reference)
#include <cuda_runtime.h>
#include <cuda_fp16.h>
#include <math.h>
#include <cstdint>
#include <cstddef>

#define NN    50000
#define NE    800000
#define NG    256
#define D_IN  128
#define D_HID 64
#define D_OUT 128

// ---------------- device scratch (no allocations allowed) ----------------
__device__ int   g_deg[NN];
__device__ int   g_fill[NN];
__device__ int   g_rowptr[NN + 1];
__device__ float g_dinv[NN];
__device__ int   g_src[NE];
__device__ int   g_dst[NE];
__device__ __align__(16) int2 g_edge[NE];        // (src, norm-as-int)
__device__ __align__(16) __half g_x16[(size_t)NN * D_IN];
__device__ __align__(16) __half g_Wt1[D_HID * D_IN];   // [n][k] fp16
__device__ __align__(16) __half g_Wt2[D_HID * D_HID];  // [n][k] fp16
__device__ __align__(16) __half g_bufA[(size_t)NN * D_HID];
__device__ __align__(16) __half g_bufB[(size_t)NN * D_HID];
__device__ float g_psum[NG * D_HID];
__device__ int   g_pcnt[NG];
__device__ int   g_idx64;

// ---------------- helpers ----------------
__device__ __forceinline__ float gelu_fast(float x) {
  float s = x + 0.044715f * x * x * x;
  return __fdividef(x, 1.0f + __expf(-1.59576912f * s));
}

__device__ __forceinline__ int load_idx(const void* p, long long i) {
  if (g_idx64) return (int)((const long long*)p)[i];
  return ((const int*)p)[i];
}

// ---------------- init: detect + zero + weight transpose to fp16 ----------
__global__ void init_kernel(const void* __restrict__ ei, int N,
                            const float* __restrict__ W1,
                            const float* __restrict__ W2) {
  int i = blockIdx.x * blockDim.x + threadIdx.x;
  if (i == 0) {
    const long long* p = (const long long*)ei;
    int ok = 1;
    for (int k = 0; k < 64; k++) {
      long long v = p[k];
      if (v < 0 || v >= (long long)N) { ok = 0; break; }
    }
    g_idx64 = ok;
  }
  if (i < N) { g_deg[i] = 0; g_fill[i] = 0; }
  if (i < NG * D_HID) g_psum[i] = 0.0f;
  if (i < NG) g_pcnt[i] = 0;
  // Wt1[n][k] = W1[k][n]   (8192 elems)
  if (i < D_HID * D_IN) {
    int n = i / D_IN, k = i % D_IN;
    g_Wt1[i] = __float2half(W1[(size_t)k * D_HID + n]);
  }
  // Wt2[n][k] = W2[k][n]   (4096 elems)
  if (i < D_HID * D_HID) {
    int n = i / D_HID, k = i % D_HID;
    g_Wt2[i] = __float2half(W2[(size_t)k * D_HID + n]);
  }
}

// ---- K1: x fp32 -> fp16 conversion blocks + histogram blocks --------------
__global__ void fused_convert_hist(const void* __restrict__ ei, int E,
                                   const float* __restrict__ x,
                                   int convBlocks, int convThreads) {
  if ((int)blockIdx.x < convBlocks) {
    int i = blockIdx.x * blockDim.x + threadIdx.x;   // one float4 per thread
    if (i < convThreads) {
      float4 v = __ldg(reinterpret_cast<const float4*>(x) + i);
      __half2 h0 = __floats2half2_rn(v.x, v.y);
      __half2 h1 = __floats2half2_rn(v.z, v.w);
      uint2 u = make_uint2(*reinterpret_cast<unsigned*>(&h0),
                           *reinterpret_cast<unsigned*>(&h1));
      reinterpret_cast<uint2*>(g_x16)[i] = u;
    }
    return;
  }
  int e = (blockIdx.x - convBlocks) * blockDim.x + threadIdx.x;
  if (e >= E) return;
  int s = load_idx(ei, e);
  int d = load_idx(ei, (long long)E + e);
  g_src[e] = s;
  g_dst[e] = d;
  atomicAdd(&g_deg[d], 1);
}

// 256-thread exclusive scan of g_deg -> g_rowptr, fused dinv
__device__ __forceinline__ void scan_body(int n) {
  __shared__ int sums[256];
  int tid   = threadIdx.x;
  int chunk = (n + 255) >> 8;
  int start = tid * chunk;
  int end   = min(start + chunk, n);
  int s = 0;
  for (int i = start; i < end; i++) s += g_deg[i];
  sums[tid] = s;
  __syncthreads();
  for (int off = 1; off < 256; off <<= 1) {
    int v = 0;
    if (tid >= off) v = sums[tid - off];
    __syncthreads();
    sums[tid] += v;
    __syncthreads();
  }
  int run = (tid == 0) ? 0 : sums[tid - 1];
  for (int i = start; i < end; i++) {
    int d = g_deg[i];
    g_rowptr[i] = run;
    g_dinv[i]   = rsqrtf((float)d + 1.0f);   // self-loop: deg+1
    run += d;
  }
  if (end == n && start < n) g_rowptr[n] = run;
}

// ---------------- tensor-core GEMM: H[M,64] = X[M,K] @ Wt^T ----------------
// mma.sync.m16n8k16 fp16xfp16 -> fp32. Warp computes 32 rows x 64 cols.
// Block = 8 warps = 256 rows. All operands straight from global (no smem).
__device__ __forceinline__ void mma16816(float* c, const unsigned* a,
                                         const unsigned* b) {
  asm volatile(
      "mma.sync.aligned.m16n8k16.row.col.f32.f16.f16.f32 "
      "{%0,%1,%2,%3}, {%4,%5,%6,%7}, {%8,%9}, {%0,%1,%2,%3};"
      : "+f"(c[0]), "+f"(c[1]), "+f"(c[2]), "+f"(c[3])
      : "r"(a[0]), "r"(a[1]), "r"(a[2]), "r"(a[3]), "r"(b[0]), "r"(b[1]));
}

template <int K>
__device__ __forceinline__ void gemm_mma_body(const __half* __restrict__ X,
                                              const __half* __restrict__ Wt,
                                              __half* __restrict__ H, int M,
                                              int bid) {
  int warp = threadIdx.x >> 5, lane = threadIdx.x & 31;
  int g = lane >> 2, t = lane & 3;
  int row0 = bid * 256 + warp * 32;

  float acc[2][8][4];
#pragma unroll
  for (int rt = 0; rt < 2; rt++)
#pragma unroll
    for (int j = 0; j < 8; j++)
#pragma unroll
      for (int c = 0; c < 4; c++) acc[rt][j][c] = 0.0f;

#pragma unroll
  for (int k0 = 0; k0 < K; k0 += 16) {
    unsigned a[2][4];
#pragma unroll
    for (int rt = 0; rt < 2; rt++) {
      int ra = row0 + rt * 16 + g;
      int rb = ra + 8;
      if (ra >= M) ra = M - 1;          // clamp: OOB rows discarded at store
      if (rb >= M) rb = M - 1;
      const unsigned* pa =
          reinterpret_cast<const unsigned*>(X + (size_t)ra * K + k0);
      const unsigned* pb =
          reinterpret_cast<const unsigned*>(X + (size_t)rb * K + k0);
      a[rt][0] = pa[t];
      a[rt][1] = pb[t];
      a[rt][2] = pa[t + 4];
      a[rt][3] = pb[t + 4];
    }
#pragma unroll
    for (int j = 0; j < 8; j++) {
      int col = j * 8 + g;
      const unsigned* pw =
          reinterpret_cast<const unsigned*>(Wt + (size_t)col * K + k0);
      unsigned b[2] = {pw[t], pw[t + 4]};
      mma16816(acc[0][j], a[0], b);
      mma16816(acc[1][j], a[1], b);
    }
  }

#pragma unroll
  for (int rt = 0; rt < 2; rt++) {
    int r1 = row0 + rt * 16 + g;
    int r2 = r1 + 8;
#pragma unroll
    for (int j = 0; j < 8; j++) {
      int col = j * 8 + t * 2;
      if (r1 < M) {
        __half2 h = __floats2half2_rn(acc[rt][j][0], acc[rt][j][1]);
        *reinterpret_cast<__half2*>(H + (size_t)r1 * D_HID + col) = h;
      }
      if (r2 < M) {
        __half2 h = __floats2half2_rn(acc[rt][j][2], acc[rt][j][3]);
        *reinterpret_cast<__half2*>(H + (size_t)r2 * D_HID + col) = h;
      }
    }
  }
}

// ---- K2: scan block (blockIdx 0) + all GEMM1 blocks ------------------------
__global__ void __launch_bounds__(256)
fused_scan_gemm1(int N, __half* __restrict__ H, int M) {
  if (blockIdx.x == 0) {
    scan_body(N);
    return;
  }
  gemm_mma_body<D_IN>(g_x16, g_Wt1, H, M, blockIdx.x - 1);
}

// ---- K3: scatter alone, full occupancy -------------------------------------
__global__ void scatter_kernel(int E) {
  int e = blockIdx.x * blockDim.x + threadIdx.x;
  if (e >= E) return;
  int s = g_src[e];
  int d = g_dst[e];
  int pos = g_rowptr[d] + atomicAdd(&g_fill[d], 1);
  g_edge[pos] = make_int2(s, __float_as_int(g_dinv[s] * g_dinv[d]));
}

// ---- GEMM2 (layer 2): bufB fp16 -> bufA fp16 -------------------------------
__global__ void __launch_bounds__(256)
gemm2_kernel(const __half* __restrict__ X, __half* __restrict__ H, int M) {
  gemm_mma_body<D_HID>(X, g_Wt2, H, M, blockIdx.x);
}

// ------- CSR aggregation core (F=64, warp/node, fp16 gather, MLP=4) --------
__device__ __forceinline__ float2 agg_node(const __half* __restrict__ H,
                                           int n, int lane) {
  float dn = g_dinv[n];
  float ws = dn * dn;
  float2 self = __half22float2(
      __ldg(reinterpret_cast<const __half2*>(H + (size_t)n * D_HID) + lane));
  float a0 = self.x * ws, a1 = self.y * ws;

  int e  = g_rowptr[n];
  int e1 = g_rowptr[n + 1];
  for (; e + 3 < e1; e += 4) {
    int2 v0 = __ldg(&g_edge[e]);
    int2 v1 = __ldg(&g_edge[e + 1]);
    int2 v2 = __ldg(&g_edge[e + 2]);
    int2 v3 = __ldg(&g_edge[e + 3]);
    float2 h0 = __half22float2(
        __ldg(reinterpret_cast<const __half2*>(H + (size_t)v0.x * D_HID) + lane));
    float2 h1 = __half22float2(
        __ldg(reinterpret_cast<const __half2*>(H + (size_t)v1.x * D_HID) + lane));
    float2 h2 = __half22float2(
        __ldg(reinterpret_cast<const __half2*>(H + (size_t)v2.x * D_HID) + lane));
    float2 h3 = __half22float2(
        __ldg(reinterpret_cast<const __half2*>(H + (size_t)v3.x * D_HID) + lane));
    float w0 = __int_as_float(v0.y);
    float w1 = __int_as_float(v1.y);
    float w2 = __int_as_float(v2.y);
    float w3 = __int_as_float(v3.y);
    a0 += w0 * h0.x; a1 += w0 * h0.y;
    a0 += w1 * h1.x; a1 += w1 * h1.y;
    a0 += w2 * h2.x; a1 += w2 * h2.y;
    a0 += w3 * h3.x; a1 += w3 * h3.y;
  }
  for (; e < e1; e++) {
    int2 v = __ldg(&g_edge[e]);
    float2 h = __half22float2(
        __ldg(reinterpret_cast<const __half2*>(H + (size_t)v.x * D_HID) + lane));
    float w = __int_as_float(v.y);
    a0 += w * h.x; a1 += w * h.y;
  }
  return make_float2(a0, a1);
}

__global__ void agg_gelu_kernel(const __half* __restrict__ H,
                                const float* __restrict__ bias,
                                __half* __restrict__ out, int N) {
  int t = blockIdx.x * blockDim.x + threadIdx.x;
  int n = t >> 5, lane = t & 31;
  if (n >= N) return;
  float2 a = agg_node(H, n, lane);
  float2 b = __ldg(reinterpret_cast<const float2*>(bias) + lane);
  float y0 = gelu_fast(a.x + b.x);
  float y1 = gelu_fast(a.y + b.y);
  reinterpret_cast<__half2*>(out + (size_t)n * D_HID)[lane] =
      __floats2half2_rn(y0, y1);
}

// ------- layer-3 agg fused with mean-pool; batch sorted -> smem reduce -----
__global__ void agg_pool_kernel(const __half* __restrict__ H,
                                const void* __restrict__ batch, int N) {
  __shared__ float sacc[D_HID];
  __shared__ int   scnt;
  __shared__ int   sg;
  int tid  = threadIdx.x;
  int lane = tid & 31, wid = tid >> 5;
  int n = blockIdx.x * 8 + wid;

  if (tid == 0) {
    scnt = 0;
    int first = blockIdx.x * 8;
    sg = load_idx(batch, first < N ? first : (N - 1));
  }
  if (tid < D_HID) sacc[tid] = 0.0f;
  __syncthreads();

  if (n < N) {
    float2 a = agg_node(H, n, lane);
    int g = load_idx(batch, n);
    if (g == sg) {
      atomicAdd(&sacc[lane * 2],     a.x);
      atomicAdd(&sacc[lane * 2 + 1], a.y);
      if (lane == 0) atomicAdd(&scnt, 1);
    } else {
      atomicAdd(&g_psum[g * D_HID + lane * 2],     a.x);
      atomicAdd(&g_psum[g * D_HID + lane * 2 + 1], a.y);
      if (lane == 0) atomicAdd(&g_pcnt[g], 1);
    }
  }
  __syncthreads();
  if (scnt > 0) {
    if (tid < D_HID) atomicAdd(&g_psum[sg * D_HID + tid], sacc[tid]);
    if (tid == 0)    atomicAdd(&g_pcnt[sg], scnt);
  }
}

// ------- final tiny GEMM: out[g,:] = mean_g @ W3 + b3 -----------------------
__global__ void final_gemm_kernel(const float* __restrict__ W3,
                                  const float* __restrict__ b3,
                                  float* __restrict__ out) {
  int g = blockIdx.x;
  int j = threadIdx.x;  // 128 threads = D_OUT
  __shared__ float row[D_HID];
  int cnt = g_pcnt[g];
  float inv = (cnt > 0) ? (1.0f / (float)cnt) : 0.0f;
  if (j < D_HID) row[j] = g_psum[g * D_HID + j] * inv;
  __syncthreads();
  float acc = (cnt > 0) ? __ldg(&b3[j]) : 0.0f;
#pragma unroll 8
  for (int k = 0; k < D_HID; k++) acc += row[k] * __ldg(&W3[k * D_OUT + j]);
  out[(size_t)g * D_OUT + j] = acc;
}

// ---------------- launch ----------------
extern "C" void kernel_launch(void* const* d_in, const int* in_sizes, int n_in,
                              void* d_out, int out_size) {
  const float* x     = (const float*)d_in[0];
  const void*  ei    = d_in[1];
  const void*  batch = d_in[2];

  int wi = 3;
  while (wi < n_in && in_sizes[wi] <= 1) wi++;
  const float* W1 = (const float*)d_in[wi + 0];
  const float* b1 = (const float*)d_in[wi + 1];
  const float* W2 = (const float*)d_in[wi + 2];
  const float* b2 = (const float*)d_in[wi + 3];
  const float* W3 = (const float*)d_in[wi + 4];
  const float* b3 = (const float*)d_in[wi + 5];

  int N = in_sizes[2];
  int E = in_sizes[1] / 2;

  __half *bufA, *bufB;
  cudaGetSymbolAddress((void**)&bufA, g_bufA);
  cudaGetSymbolAddress((void**)&bufB, g_bufB);

  const int TB = 256;
  int nb_nodes = (N + TB - 1) / TB;
  int nb_edges = (E + TB - 1) / TB;
  int nb_warp  = (int)(((long long)N * 32 + TB - 1) / TB);
  int nb_mma   = (N + 255) / 256;

  int convThreads = (N * D_IN) / 4;                 // one float4 per thread
  int convBlocks  = (convThreads + TB - 1) / TB;

  // K0: init + detect + weight transpose (fp16)
  init_kernel<<<nb_nodes, TB>>>(ei, N, W1, W2);
  // K1: x->fp16 conversion || histogram (both high-occupancy)
  fused_convert_hist<<<convBlocks + nb_edges, TB>>>(ei, E, x, convBlocks,
                                                    convThreads);
  // K2: rowptr scan (block 0) || all of GEMM1 (tensor cores)
  fused_scan_gemm1<<<1 + nb_mma, TB>>>(N, bufA, N);
  // K3: CSR scatter at full occupancy
  scatter_kernel<<<nb_edges, TB>>>(E);

  // layer 1 aggregation + gelu
  agg_gelu_kernel<<<nb_warp, TB>>>(bufA, b1, bufB, N);

  // layer 2: tensor-core GEMM 64->64, agg + gelu
  gemm2_kernel<<<nb_mma, TB>>>(bufB, bufA, N);
  agg_gelu_kernel<<<nb_warp, TB>>>(bufA, b2, bufB, N);

  // layer 3 (reordered): agg+pool in 64-dim, then [NG,64]@[64,128]+b3
  agg_pool_kernel<<<(N + 7) / 8, TB>>>(bufB, batch, N);
  final_gemm_kernel<<<out_size / D_OUT, D_OUT>>>(W3, b3, (float*)d_out);
}

// round 16
// speedup vs baseline: 1.0086x; 1.0086x over previous
#include <cuda_runtime.h>
#include <cuda_fp16.h>
#include <math.h>
#include <cstdint>
#include <cstddef>

#define NN    50000
#define NE    800000
#define NG    256
#define D_IN  128
#define D_HID 64
#define D_OUT 128

// ---------------- device scratch (no allocations allowed) ----------------
__device__ int   g_deg[NN];
__device__ int   g_fill[NN];
__device__ int   g_rowptr[NN + 1];
__device__ float g_dinv[NN];
__device__ __align__(16) int g_src[NE];
__device__ __align__(16) int g_dst[NE];
__device__ __align__(16) int2 g_edge[NE];        // (src, norm-as-int)
__device__ __align__(16) __half g_x16[(size_t)NN * D_IN];
__device__ __align__(16) __half g_Wt1[D_HID * D_IN];   // [n][k] fp16
__device__ __align__(16) __half g_Wt2[D_HID * D_HID];  // [n][k] fp16
__device__ __align__(16) __half g_bufA[(size_t)NN * D_HID];
__device__ __align__(16) __half g_bufB[(size_t)NN * D_HID];
__device__ float g_psum[NG * D_HID];
__device__ int   g_pcnt[NG];
__device__ int   g_idx64;

// ---------------- helpers ----------------
__device__ __forceinline__ float gelu_fast(float x) {
  float s = x + 0.044715f * x * x * x;
  return __fdividef(x, 1.0f + __expf(-1.59576912f * s));
}

__device__ __forceinline__ int load_idx(const void* p, long long i) {
  if (g_idx64) return (int)((const long long*)p)[i];
  return ((const int*)p)[i];
}

// ---------------- init: detect + zero + weight transpose to fp16 ----------
__global__ void init_kernel(const void* __restrict__ ei, int N,
                            const float* __restrict__ W1,
                            const float* __restrict__ W2) {
  int i = blockIdx.x * blockDim.x + threadIdx.x;
  if (i == 0) {
    const long long* p = (const long long*)ei;
    int ok = 1;
    for (int k = 0; k < 64; k++) {
      long long v = p[k];
      if (v < 0 || v >= (long long)N) { ok = 0; break; }
    }
    g_idx64 = ok;
  }
  if (i < N) { g_deg[i] = 0; g_fill[i] = 0; }
  if (i < NG * D_HID) g_psum[i] = 0.0f;
  if (i < NG) g_pcnt[i] = 0;
  if (i < D_HID * D_IN) {
    int n = i / D_IN, k = i % D_IN;
    g_Wt1[i] = __float2half(W1[(size_t)k * D_HID + n]);
  }
  if (i < D_HID * D_HID) {
    int n = i / D_HID, k = i % D_HID;
    g_Wt2[i] = __float2half(W2[(size_t)k * D_HID + n]);
  }
}

// ---- K1: x fp32 -> fp16 conversion blocks + histogram blocks (4 edges/thr) -
__global__ void fused_convert_hist(const void* __restrict__ ei, int E,
                                   const float* __restrict__ x,
                                   int convBlocks, int convThreads) {
  if ((int)blockIdx.x < convBlocks) {
    int i = blockIdx.x * blockDim.x + threadIdx.x;   // one float4 per thread
    if (i < convThreads) {
      float4 v = __ldg(reinterpret_cast<const float4*>(x) + i);
      __half2 h0 = __floats2half2_rn(v.x, v.y);
      __half2 h1 = __floats2half2_rn(v.z, v.w);
      uint2 u = make_uint2(*reinterpret_cast<unsigned*>(&h0),
                           *reinterpret_cast<unsigned*>(&h1));
      reinterpret_cast<uint2*>(g_x16)[i] = u;
    }
    return;
  }
  int base = ((blockIdx.x - convBlocks) * blockDim.x + threadIdx.x) * 4;
  if (base >= E) return;
  int s[4], d[4];
  if (base + 3 < E && (E & 3) == 0) {
    if (g_idx64) {
      const longlong2* p = reinterpret_cast<const longlong2*>(ei);
      longlong2 s01 = __ldg(&p[base >> 1]);
      longlong2 s23 = __ldg(&p[(base >> 1) + 1]);
      long long off = ((long long)E + base) >> 1;
      longlong2 d01 = __ldg(&p[off]);
      longlong2 d23 = __ldg(&p[off + 1]);
      s[0] = (int)s01.x; s[1] = (int)s01.y; s[2] = (int)s23.x; s[3] = (int)s23.y;
      d[0] = (int)d01.x; d[1] = (int)d01.y; d[2] = (int)d23.x; d[3] = (int)d23.y;
    } else {
      const int4* p = reinterpret_cast<const int4*>(ei);
      int4 sv = __ldg(&p[base >> 2]);
      int4 dv = __ldg(&p[(E + base) >> 2]);
      s[0] = sv.x; s[1] = sv.y; s[2] = sv.z; s[3] = sv.w;
      d[0] = dv.x; d[1] = dv.y; d[2] = dv.z; d[3] = dv.w;
    }
    *reinterpret_cast<int4*>(&g_src[base]) = make_int4(s[0], s[1], s[2], s[3]);
    *reinterpret_cast<int4*>(&g_dst[base]) = make_int4(d[0], d[1], d[2], d[3]);
#pragma unroll
    for (int i = 0; i < 4; i++) atomicAdd(&g_deg[d[i]], 1);
  } else {
    for (int e = base; e < E && e < base + 4; e++) {
      int ss = load_idx(ei, e);
      int dd = load_idx(ei, (long long)E + e);
      g_src[e] = ss;
      g_dst[e] = dd;
      atomicAdd(&g_deg[dd], 1);
    }
  }
}

// 256-thread exclusive scan of g_deg -> g_rowptr, fused dinv
__device__ __forceinline__ void scan_body(int n) {
  __shared__ int sums[256];
  int tid   = threadIdx.x;
  int chunk = (n + 255) >> 8;
  int start = tid * chunk;
  int end   = min(start + chunk, n);
  int s = 0;
  for (int i = start; i < end; i++) s += g_deg[i];
  sums[tid] = s;
  __syncthreads();
  for (int off = 1; off < 256; off <<= 1) {
    int v = 0;
    if (tid >= off) v = sums[tid - off];
    __syncthreads();
    sums[tid] += v;
    __syncthreads();
  }
  int run = (tid == 0) ? 0 : sums[tid - 1];
  for (int i = start; i < end; i++) {
    int d = g_deg[i];
    g_rowptr[i] = run;
    g_dinv[i]   = rsqrtf((float)d + 1.0f);   // self-loop: deg+1
    run += d;
  }
  if (end == n && start < n) g_rowptr[n] = run;
}

// ---------------- tensor-core GEMM: H[M,64] = X[M,K] @ Wt^T ----------------
__device__ __forceinline__ void mma16816(float* c, const unsigned* a,
                                         const unsigned* b) {
  asm volatile(
      "mma.sync.aligned.m16n8k16.row.col.f32.f16.f16.f32 "
      "{%0,%1,%2,%3}, {%4,%5,%6,%7}, {%8,%9}, {%0,%1,%2,%3};"
      : "+f"(c[0]), "+f"(c[1]), "+f"(c[2]), "+f"(c[3])
      : "r"(a[0]), "r"(a[1]), "r"(a[2]), "r"(a[3]), "r"(b[0]), "r"(b[1]));
}

template <int K>
__device__ __forceinline__ void gemm_mma_body(const __half* __restrict__ X,
                                              const __half* __restrict__ Wt,
                                              __half* __restrict__ H, int M,
                                              int bid) {
  int warp = threadIdx.x >> 5, lane = threadIdx.x & 31;
  int g = lane >> 2, t = lane & 3;
  int row0 = bid * 256 + warp * 32;

  float acc[2][8][4];
#pragma unroll
  for (int rt = 0; rt < 2; rt++)
#pragma unroll
    for (int j = 0; j < 8; j++)
#pragma unroll
      for (int c = 0; c < 4; c++) acc[rt][j][c] = 0.0f;

#pragma unroll
  for (int k0 = 0; k0 < K; k0 += 16) {
    unsigned a[2][4];
#pragma unroll
    for (int rt = 0; rt < 2; rt++) {
      int ra = row0 + rt * 16 + g;
      int rb = ra + 8;
      if (ra >= M) ra = M - 1;
      if (rb >= M) rb = M - 1;
      const unsigned* pa =
          reinterpret_cast<const unsigned*>(X + (size_t)ra * K + k0);
      const unsigned* pb =
          reinterpret_cast<const unsigned*>(X + (size_t)rb * K + k0);
      a[rt][0] = pa[t];
      a[rt][1] = pb[t];
      a[rt][2] = pa[t + 4];
      a[rt][3] = pb[t + 4];
    }
#pragma unroll
    for (int j = 0; j < 8; j++) {
      int col = j * 8 + g;
      const unsigned* pw =
          reinterpret_cast<const unsigned*>(Wt + (size_t)col * K + k0);
      unsigned b[2] = {pw[t], pw[t + 4]};
      mma16816(acc[0][j], a[0], b);
      mma16816(acc[1][j], a[1], b);
    }
  }

#pragma unroll
  for (int rt = 0; rt < 2; rt++) {
    int r1 = row0 + rt * 16 + g;
    int r2 = r1 + 8;
#pragma unroll
    for (int j = 0; j < 8; j++) {
      int col = j * 8 + t * 2;
      if (r1 < M) {
        __half2 h = __floats2half2_rn(acc[rt][j][0], acc[rt][j][1]);
        *reinterpret_cast<__half2*>(H + (size_t)r1 * D_HID + col) = h;
      }
      if (r2 < M) {
        __half2 h = __floats2half2_rn(acc[rt][j][2], acc[rt][j][3]);
        *reinterpret_cast<__half2*>(H + (size_t)r2 * D_HID + col) = h;
      }
    }
  }
}

// ---- K2: scan block (blockIdx 0) + all GEMM1 blocks ------------------------
__global__ void __launch_bounds__(256)
fused_scan_gemm1(int N, __half* __restrict__ H, int M) {
  if (blockIdx.x == 0) {
    scan_body(N);
    return;
  }
  gemm_mma_body<D_IN>(g_x16, g_Wt1, H, M, blockIdx.x - 1);
}

// ---- K3: scatter, 4 edges/thread (4 independent atomic->store chains) -----
__global__ void scatter_kernel(int E) {
  int base = (blockIdx.x * blockDim.x + threadIdx.x) * 4;
  if (base >= E) return;
  if (base + 3 < E) {
    int4 sv = *reinterpret_cast<const int4*>(&g_src[base]);
    int4 dv = *reinterpret_cast<const int4*>(&g_dst[base]);
    int s[4] = {sv.x, sv.y, sv.z, sv.w};
    int d[4] = {dv.x, dv.y, dv.z, dv.w};
#pragma unroll
    for (int i = 0; i < 4; i++) {
      int pos = g_rowptr[d[i]] + atomicAdd(&g_fill[d[i]], 1);
      g_edge[pos] = make_int2(s[i], __float_as_int(g_dinv[s[i]] * g_dinv[d[i]]));
    }
  } else {
    for (int e = base; e < E; e++) {
      int s = g_src[e], d = g_dst[e];
      int pos = g_rowptr[d] + atomicAdd(&g_fill[d], 1);
      g_edge[pos] = make_int2(s, __float_as_int(g_dinv[s] * g_dinv[d]));
    }
  }
}

// ---- GEMM2 (layer 2): bufB fp16 -> bufA fp16 -------------------------------
__global__ void __launch_bounds__(256)
gemm2_kernel(const __half* __restrict__ X, __half* __restrict__ H, int M) {
  gemm_mma_body<D_HID>(X, g_Wt2, H, M, blockIdx.x);
}

// ------- CSR aggregation core (F=64, warp/node, fp16 gather, MLP=8) --------
__device__ __forceinline__ float2 agg_node(const __half* __restrict__ H,
                                           int n, int lane) {
  float dn = g_dinv[n];
  float ws = dn * dn;
  float2 self = __half22float2(
      __ldg(reinterpret_cast<const __half2*>(H + (size_t)n * D_HID) + lane));
  float a0 = self.x * ws, a1 = self.y * ws;

  int e  = g_rowptr[n];
  int e1 = g_rowptr[n + 1];
  // 8-wide unroll: 8 independent row gathers in flight per warp
  for (; e + 7 < e1; e += 8) {
    int2 v[8];
    float2 h[8];
#pragma unroll
    for (int i = 0; i < 8; i++) v[i] = __ldg(&g_edge[e + i]);
#pragma unroll
    for (int i = 0; i < 8; i++)
      h[i] = __half22float2(
          __ldg(reinterpret_cast<const __half2*>(H + (size_t)v[i].x * D_HID) +
                lane));
#pragma unroll
    for (int i = 0; i < 8; i++) {
      float w = __int_as_float(v[i].y);
      a0 += w * h[i].x;
      a1 += w * h[i].y;
    }
  }
  for (; e + 3 < e1; e += 4) {
    int2 v[4];
    float2 h[4];
#pragma unroll
    for (int i = 0; i < 4; i++) v[i] = __ldg(&g_edge[e + i]);
#pragma unroll
    for (int i = 0; i < 4; i++)
      h[i] = __half22float2(
          __ldg(reinterpret_cast<const __half2*>(H + (size_t)v[i].x * D_HID) +
                lane));
#pragma unroll
    for (int i = 0; i < 4; i++) {
      float w = __int_as_float(v[i].y);
      a0 += w * h[i].x;
      a1 += w * h[i].y;
    }
  }
  for (; e < e1; e++) {
    int2 v = __ldg(&g_edge[e]);
    float2 h = __half22float2(
        __ldg(reinterpret_cast<const __half2*>(H + (size_t)v.x * D_HID) + lane));
    float w = __int_as_float(v.y);
    a0 += w * h.x;
    a1 += w * h.y;
  }
  return make_float2(a0, a1);
}

__global__ void agg_gelu_kernel(const __half* __restrict__ H,
                                const float* __restrict__ bias,
                                __half* __restrict__ out, int N) {
  int t = blockIdx.x * blockDim.x + threadIdx.x;
  int n = t >> 5, lane = t & 31;
  if (n >= N) return;
  float2 a = agg_node(H, n, lane);
  float2 b = __ldg(reinterpret_cast<const float2*>(bias) + lane);
  float y0 = gelu_fast(a.x + b.x);
  float y1 = gelu_fast(a.y + b.y);
  reinterpret_cast<__half2*>(out + (size_t)n * D_HID)[lane] =
      __floats2half2_rn(y0, y1);
}

// ------- layer-3 agg fused with mean-pool; batch sorted -> smem reduce -----
__global__ void agg_pool_kernel(const __half* __restrict__ H,
                                const void* __restrict__ batch, int N) {
  __shared__ float sacc[D_HID];
  __shared__ int   scnt;
  __shared__ int   sg;
  int tid  = threadIdx.x;
  int lane = tid & 31, wid = tid >> 5;
  int n = blockIdx.x * 8 + wid;

  if (tid == 0) {
    scnt = 0;
    int first = blockIdx.x * 8;
    sg = load_idx(batch, first < N ? first : (N - 1));
  }
  if (tid < D_HID) sacc[tid] = 0.0f;
  __syncthreads();

  if (n < N) {
    float2 a = agg_node(H, n, lane);
    int g = load_idx(batch, n);
    if (g == sg) {
      atomicAdd(&sacc[lane * 2],     a.x);
      atomicAdd(&sacc[lane * 2 + 1], a.y);
      if (lane == 0) atomicAdd(&scnt, 1);
    } else {
      atomicAdd(&g_psum[g * D_HID + lane * 2],     a.x);
      atomicAdd(&g_psum[g * D_HID + lane * 2 + 1], a.y);
      if (lane == 0) atomicAdd(&g_pcnt[g], 1);
    }
  }
  __syncthreads();
  if (scnt > 0) {
    if (tid < D_HID) atomicAdd(&g_psum[sg * D_HID + tid], sacc[tid]);
    if (tid == 0)    atomicAdd(&g_pcnt[sg], scnt);
  }
}

// ------- final tiny GEMM: out[g,:] = mean_g @ W3 + b3 -----------------------
__global__ void final_gemm_kernel(const float* __restrict__ W3,
                                  const float* __restrict__ b3,
                                  float* __restrict__ out) {
  int g = blockIdx.x;
  int j = threadIdx.x;  // 128 threads = D_OUT
  __shared__ float row[D_HID];
  int cnt = g_pcnt[g];
  float inv = (cnt > 0) ? (1.0f / (float)cnt) : 0.0f;
  if (j < D_HID) row[j] = g_psum[g * D_HID + j] * inv;
  __syncthreads();
  float acc = (cnt > 0) ? __ldg(&b3[j]) : 0.0f;
#pragma unroll 8
  for (int k = 0; k < D_HID; k++) acc += row[k] * __ldg(&W3[k * D_OUT + j]);
  out[(size_t)g * D_OUT + j] = acc;
}

// ---------------- launch ----------------
extern "C" void kernel_launch(void* const* d_in, const int* in_sizes, int n_in,
                              void* d_out, int out_size) {
  const float* x     = (const float*)d_in[0];
  const void*  ei    = d_in[1];
  const void*  batch = d_in[2];

  int wi = 3;
  while (wi < n_in && in_sizes[wi] <= 1) wi++;
  const float* W1 = (const float*)d_in[wi + 0];
  const float* b1 = (const float*)d_in[wi + 1];
  const float* W2 = (const float*)d_in[wi + 2];
  const float* b2 = (const float*)d_in[wi + 3];
  const float* W3 = (const float*)d_in[wi + 4];
  const float* b3 = (const float*)d_in[wi + 5];

  int N = in_sizes[2];
  int E = in_sizes[1] / 2;

  __half *bufA, *bufB;
  cudaGetSymbolAddress((void**)&bufA, g_bufA);
  cudaGetSymbolAddress((void**)&bufB, g_bufB);

  const int TB = 256;
  int nb_nodes  = (N + TB - 1) / TB;
  int nb_edges4 = ((E + 3) / 4 + TB - 1) / TB;   // 4 edges per thread
  int nb_warp   = (int)(((long long)N * 32 + TB - 1) / TB);
  int nb_mma    = (N + 255) / 256;

  int convThreads = (N * D_IN) / 4;
  int convBlocks  = (convThreads + TB - 1) / TB;

  // K0: init + detect + weight transpose (fp16)
  init_kernel<<<nb_nodes, TB>>>(ei, N, W1, W2);
  // K1: x->fp16 conversion || histogram (4 edges/thread)
  fused_convert_hist<<<convBlocks + nb_edges4, TB>>>(ei, E, x, convBlocks,
                                                     convThreads);
  // K2: rowptr scan (block 0) || all of GEMM1 (tensor cores)
  fused_scan_gemm1<<<1 + nb_mma, TB>>>(N, bufA, N);
  // K3: CSR scatter (4 edges/thread, full occupancy)
  scatter_kernel<<<nb_edges4, TB>>>(E);

  // layer 1 aggregation + gelu
  agg_gelu_kernel<<<nb_warp, TB>>>(bufA, b1, bufB, N);

  // layer 2: tensor-core GEMM 64->64, agg + gelu
  gemm2_kernel<<<nb_mma, TB>>>(bufB, bufA, N);
  agg_gelu_kernel<<<nb_warp, TB>>>(bufA, b2, bufB, N);

  // layer 3 (reordered): agg+pool in 64-dim, then [NG,64]@[64,128]+b3
  agg_pool_kernel<<<(N + 7) / 8, TB>>>(bufB, batch, N);
  final_gemm_kernel<<<out_size / D_OUT, D_OUT>>>(W3, b3, (float*)d_out);
}

// round 17
// speedup vs baseline: 1.0093x; 1.0007x over previous
#include <cuda_runtime.h>
#include <cuda_fp16.h>
#include <math.h>
#include <cstdint>
#include <cstddef>

#define NN    50000
#define NE    800000
#define NG    256
#define D_IN  128
#define D_HID 64
#define D_OUT 128

// ---------------- device scratch (no allocations allowed) ----------------
__device__ int   g_deg[NN];
__device__ int   g_fill[NN];
__device__ int   g_rowptr[NN + 1];
__device__ float g_dinv[NN];
__device__ __align__(16) int g_src[NE];
__device__ __align__(16) int g_dst[NE];
__device__ __align__(16) int2 g_edge[NE];        // (src, norm-as-int)
__device__ __align__(16) __half g_x16[(size_t)NN * D_IN];
__device__ __align__(16) __half g_Wt1[D_HID * D_IN];   // [n][k] fp16
__device__ __align__(16) __half g_Wt2[D_HID * D_HID];  // [n][k] fp16
__device__ __align__(16) __half g_bufA[(size_t)NN * D_HID];
__device__ __align__(16) __half g_bufB[(size_t)NN * D_HID];
__device__ float g_psum[NG * D_HID];
__device__ int   g_pcnt[NG];
__device__ int   g_idx64;

// ---------------- helpers ----------------
__device__ __forceinline__ float gelu_fast(float x) {
  float s = x + 0.044715f * x * x * x;
  return __fdividef(x, 1.0f + __expf(-1.59576912f * s));
}

__device__ __forceinline__ int load_idx(const void* p, long long i) {
  if (g_idx64) return (int)((const long long*)p)[i];
  return ((const int*)p)[i];
}

// ---------------- init: detect + zero + weight transpose to fp16 ----------
__global__ void init_kernel(const void* __restrict__ ei, int N,
                            const float* __restrict__ W1,
                            const float* __restrict__ W2) {
  int i = blockIdx.x * blockDim.x + threadIdx.x;
  if (i == 0) {
    const long long* p = (const long long*)ei;
    int ok = 1;
    for (int k = 0; k < 64; k++) {
      long long v = p[k];
      if (v < 0 || v >= (long long)N) { ok = 0; break; }
    }
    g_idx64 = ok;
  }
  if (i < N) { g_deg[i] = 0; g_fill[i] = 0; }
  if (i < NG * D_HID) g_psum[i] = 0.0f;
  if (i < NG) g_pcnt[i] = 0;
  if (i < D_HID * D_IN) {
    int n = i / D_IN, k = i % D_IN;
    g_Wt1[i] = __float2half(W1[(size_t)k * D_HID + n]);
  }
  if (i < D_HID * D_HID) {
    int n = i / D_HID, k = i % D_HID;
    g_Wt2[i] = __float2half(W2[(size_t)k * D_HID + n]);
  }
}

// ---- K1: x fp32 -> fp16 conversion blocks + histogram blocks (4 edges/thr) -
__global__ void fused_convert_hist(const void* __restrict__ ei, int E,
                                   const float* __restrict__ x,
                                   int convBlocks, int convThreads) {
  if ((int)blockIdx.x < convBlocks) {
    int i = blockIdx.x * blockDim.x + threadIdx.x;   // one float4 per thread
    if (i < convThreads) {
      float4 v = __ldg(reinterpret_cast<const float4*>(x) + i);
      __half2 h0 = __floats2half2_rn(v.x, v.y);
      __half2 h1 = __floats2half2_rn(v.z, v.w);
      uint2 u = make_uint2(*reinterpret_cast<unsigned*>(&h0),
                           *reinterpret_cast<unsigned*>(&h1));
      reinterpret_cast<uint2*>(g_x16)[i] = u;
    }
    return;
  }
  int base = ((blockIdx.x - convBlocks) * blockDim.x + threadIdx.x) * 4;
  if (base >= E) return;
  int s[4], d[4];
  if (base + 3 < E && (E & 3) == 0) {
    if (g_idx64) {
      const longlong2* p = reinterpret_cast<const longlong2*>(ei);
      longlong2 s01 = __ldg(&p[base >> 1]);
      longlong2 s23 = __ldg(&p[(base >> 1) + 1]);
      long long off = ((long long)E + base) >> 1;
      longlong2 d01 = __ldg(&p[off]);
      longlong2 d23 = __ldg(&p[off + 1]);
      s[0] = (int)s01.x; s[1] = (int)s01.y; s[2] = (int)s23.x; s[3] = (int)s23.y;
      d[0] = (int)d01.x; d[1] = (int)d01.y; d[2] = (int)d23.x; d[3] = (int)d23.y;
    } else {
      const int4* p = reinterpret_cast<const int4*>(ei);
      int4 sv = __ldg(&p[base >> 2]);
      int4 dv = __ldg(&p[(E + base) >> 2]);
      s[0] = sv.x; s[1] = sv.y; s[2] = sv.z; s[3] = sv.w;
      d[0] = dv.x; d[1] = dv.y; d[2] = dv.z; d[3] = dv.w;
    }
    *reinterpret_cast<int4*>(&g_src[base]) = make_int4(s[0], s[1], s[2], s[3]);
    *reinterpret_cast<int4*>(&g_dst[base]) = make_int4(d[0], d[1], d[2], d[3]);
#pragma unroll
    for (int i = 0; i < 4; i++) atomicAdd(&g_deg[d[i]], 1);
  } else {
    for (int e = base; e < E && e < base + 4; e++) {
      int ss = load_idx(ei, e);
      int dd = load_idx(ei, (long long)E + e);
      g_src[e] = ss;
      g_dst[e] = dd;
      atomicAdd(&g_deg[dd], 1);
    }
  }
}

// 256-thread exclusive scan of g_deg -> g_rowptr, fused dinv
__device__ __forceinline__ void scan_body(int n) {
  __shared__ int sums[256];
  int tid   = threadIdx.x;
  int chunk = (n + 255) >> 8;
  int start = tid * chunk;
  int end   = min(start + chunk, n);
  int s = 0;
  for (int i = start; i < end; i++) s += g_deg[i];
  sums[tid] = s;
  __syncthreads();
  for (int off = 1; off < 256; off <<= 1) {
    int v = 0;
    if (tid >= off) v = sums[tid - off];
    __syncthreads();
    sums[tid] += v;
    __syncthreads();
  }
  int run = (tid == 0) ? 0 : sums[tid - 1];
  for (int i = start; i < end; i++) {
    int d = g_deg[i];
    g_rowptr[i] = run;
    g_dinv[i]   = rsqrtf((float)d + 1.0f);   // self-loop: deg+1
    run += d;
  }
  if (end == n && start < n) g_rowptr[n] = run;
}

// ---------------- tensor-core GEMM: H[M,64] = X[M,K] @ Wt^T ----------------
__device__ __forceinline__ void mma16816(float* c, const unsigned* a,
                                         const unsigned* b) {
  asm volatile(
      "mma.sync.aligned.m16n8k16.row.col.f32.f16.f16.f32 "
      "{%0,%1,%2,%3}, {%4,%5,%6,%7}, {%8,%9}, {%0,%1,%2,%3};"
      : "+f"(c[0]), "+f"(c[1]), "+f"(c[2]), "+f"(c[3])
      : "r"(a[0]), "r"(a[1]), "r"(a[2]), "r"(a[3]), "r"(b[0]), "r"(b[1]));
}

template <int K>
__device__ __forceinline__ void gemm_mma_body(const __half* __restrict__ X,
                                              const __half* __restrict__ Wt,
                                              __half* __restrict__ H, int M,
                                              int bid) {
  int warp = threadIdx.x >> 5, lane = threadIdx.x & 31;
  int g = lane >> 2, t = lane & 3;
  int row0 = bid * 256 + warp * 32;

  float acc[2][8][4];
#pragma unroll
  for (int rt = 0; rt < 2; rt++)
#pragma unroll
    for (int j = 0; j < 8; j++)
#pragma unroll
      for (int c = 0; c < 4; c++) acc[rt][j][c] = 0.0f;

#pragma unroll
  for (int k0 = 0; k0 < K; k0 += 16) {
    unsigned a[2][4];
#pragma unroll
    for (int rt = 0; rt < 2; rt++) {
      int ra = row0 + rt * 16 + g;
      int rb = ra + 8;
      if (ra >= M) ra = M - 1;
      if (rb >= M) rb = M - 1;
      const unsigned* pa =
          reinterpret_cast<const unsigned*>(X + (size_t)ra * K + k0);
      const unsigned* pb =
          reinterpret_cast<const unsigned*>(X + (size_t)rb * K + k0);
      a[rt][0] = pa[t];
      a[rt][1] = pb[t];
      a[rt][2] = pa[t + 4];
      a[rt][3] = pb[t + 4];
    }
#pragma unroll
    for (int j = 0; j < 8; j++) {
      int col = j * 8 + g;
      const unsigned* pw =
          reinterpret_cast<const unsigned*>(Wt + (size_t)col * K + k0);
      unsigned b[2] = {pw[t], pw[t + 4]};
      mma16816(acc[0][j], a[0], b);
      mma16816(acc[1][j], a[1], b);
    }
  }

#pragma unroll
  for (int rt = 0; rt < 2; rt++) {
    int r1 = row0 + rt * 16 + g;
    int r2 = r1 + 8;
#pragma unroll
    for (int j = 0; j < 8; j++) {
      int col = j * 8 + t * 2;
      if (r1 < M) {
        __half2 h = __floats2half2_rn(acc[rt][j][0], acc[rt][j][1]);
        *reinterpret_cast<__half2*>(H + (size_t)r1 * D_HID + col) = h;
      }
      if (r2 < M) {
        __half2 h = __floats2half2_rn(acc[rt][j][2], acc[rt][j][3]);
        *reinterpret_cast<__half2*>(H + (size_t)r2 * D_HID + col) = h;
      }
    }
  }
}

// ---- K2: scan block (blockIdx 0) + all GEMM1 blocks ------------------------
__global__ void __launch_bounds__(256)
fused_scan_gemm1(int N, __half* __restrict__ H, int M) {
  if (blockIdx.x == 0) {
    scan_body(N);
    return;
  }
  gemm_mma_body<D_IN>(g_x16, g_Wt1, H, M, blockIdx.x - 1);
}

// ---- K3: scatter, 4 edges/thread (4 independent atomic->store chains) -----
__global__ void scatter_kernel(int E) {
  int base = (blockIdx.x * blockDim.x + threadIdx.x) * 4;
  if (base >= E) return;
  if (base + 3 < E) {
    int4 sv = *reinterpret_cast<const int4*>(&g_src[base]);
    int4 dv = *reinterpret_cast<const int4*>(&g_dst[base]);
    int s[4] = {sv.x, sv.y, sv.z, sv.w};
    int d[4] = {dv.x, dv.y, dv.z, dv.w};
#pragma unroll
    for (int i = 0; i < 4; i++) {
      int pos = g_rowptr[d[i]] + atomicAdd(&g_fill[d[i]], 1);
      g_edge[pos] = make_int2(s[i], __float_as_int(g_dinv[s[i]] * g_dinv[d[i]]));
    }
  } else {
    for (int e = base; e < E; e++) {
      int s = g_src[e], d = g_dst[e];
      int pos = g_rowptr[d] + atomicAdd(&g_fill[d], 1);
      g_edge[pos] = make_int2(s, __float_as_int(g_dinv[s] * g_dinv[d]));
    }
  }
}

// ---- GEMM2 (layer 2): bufB fp16 -> bufA fp16 -------------------------------
__global__ void __launch_bounds__(256)
gemm2_kernel(const __half* __restrict__ X, __half* __restrict__ H, int M) {
  gemm_mma_body<D_HID>(X, g_Wt2, H, M, blockIdx.x);
}

// ------- CSR aggregation core (F=64, warp/node, fp16 gather, MLP=8) --------
__device__ __forceinline__ float2 agg_node(const __half* __restrict__ H,
                                           int n, int lane) {
  float dn = g_dinv[n];
  float ws = dn * dn;
  float2 self = __half22float2(
      __ldg(reinterpret_cast<const __half2*>(H + (size_t)n * D_HID) + lane));
  float a0 = self.x * ws, a1 = self.y * ws;

  int e  = g_rowptr[n];
  int e1 = g_rowptr[n + 1];
  // 8-wide unroll: 8 independent row gathers in flight per warp
  for (; e + 7 < e1; e += 8) {
    int2 v[8];
    float2 h[8];
#pragma unroll
    for (int i = 0; i < 8; i++) v[i] = __ldg(&g_edge[e + i]);
#pragma unroll
    for (int i = 0; i < 8; i++)
      h[i] = __half22float2(
          __ldg(reinterpret_cast<const __half2*>(H + (size_t)v[i].x * D_HID) +
                lane));
#pragma unroll
    for (int i = 0; i < 8; i++) {
      float w = __int_as_float(v[i].y);
      a0 += w * h[i].x;
      a1 += w * h[i].y;
    }
  }
  for (; e + 3 < e1; e += 4) {
    int2 v[4];
    float2 h[4];
#pragma unroll
    for (int i = 0; i < 4; i++) v[i] = __ldg(&g_edge[e + i]);
#pragma unroll
    for (int i = 0; i < 4; i++)
      h[i] = __half22float2(
          __ldg(reinterpret_cast<const __half2*>(H + (size_t)v[i].x * D_HID) +
                lane));
#pragma unroll
    for (int i = 0; i < 4; i++) {
      float w = __int_as_float(v[i].y);
      a0 += w * h[i].x;
      a1 += w * h[i].y;
    }
  }
  for (; e < e1; e++) {
    int2 v = __ldg(&g_edge[e]);
    float2 h = __half22float2(
        __ldg(reinterpret_cast<const __half2*>(H + (size_t)v.x * D_HID) + lane));
    float w = __int_as_float(v.y);
    a0 += w * h.x;
    a1 += w * h.y;
  }
  return make_float2(a0, a1);
}

__global__ void agg_gelu_kernel(const __half* __restrict__ H,
                                const float* __restrict__ bias,
                                __half* __restrict__ out, int N) {
  int t = blockIdx.x * blockDim.x + threadIdx.x;
  int n = t >> 5, lane = t & 31;
  if (n >= N) return;
  float2 a = agg_node(H, n, lane);
  float2 b = __ldg(reinterpret_cast<const float2*>(bias) + lane);
  float y0 = gelu_fast(a.x + b.x);
  float y1 = gelu_fast(a.y + b.y);
  reinterpret_cast<__half2*>(out + (size_t)n * D_HID)[lane] =
      __floats2half2_rn(y0, y1);
}

// ------- layer-3 agg fused with mean-pool; batch sorted -> smem reduce -----
__global__ void agg_pool_kernel(const __half* __restrict__ H,
                                const void* __restrict__ batch, int N) {
  __shared__ float sacc[D_HID];
  __shared__ int   scnt;
  __shared__ int   sg;
  int tid  = threadIdx.x;
  int lane = tid & 31, wid = tid >> 5;
  int n = blockIdx.x * 8 + wid;

  if (tid == 0) {
    scnt = 0;
    int first = blockIdx.x * 8;
    sg = load_idx(batch, first < N ? first : (N - 1));
  }
  if (tid < D_HID) sacc[tid] = 0.0f;
  __syncthreads();

  if (n < N) {
    float2 a = agg_node(H, n, lane);
    int g = load_idx(batch, n);
    if (g == sg) {
      atomicAdd(&sacc[lane * 2],     a.x);
      atomicAdd(&sacc[lane * 2 + 1], a.y);
      if (lane == 0) atomicAdd(&scnt, 1);
    } else {
      atomicAdd(&g_psum[g * D_HID + lane * 2],     a.x);
      atomicAdd(&g_psum[g * D_HID + lane * 2 + 1], a.y);
      if (lane == 0) atomicAdd(&g_pcnt[g], 1);
    }
  }
  __syncthreads();
  if (scnt > 0) {
    if (tid < D_HID) atomicAdd(&g_psum[sg * D_HID + tid], sacc[tid]);
    if (tid == 0)    atomicAdd(&g_pcnt[sg], scnt);
  }
}

// ------- final tiny GEMM: out[g,:] = mean_g @ W3 + b3 -----------------------
__global__ void final_gemm_kernel(const float* __restrict__ W3,
                                  const float* __restrict__ b3,
                                  float* __restrict__ out) {
  int g = blockIdx.x;
  int j = threadIdx.x;  // 128 threads = D_OUT
  __shared__ float row[D_HID];
  int cnt = g_pcnt[g];
  float inv = (cnt > 0) ? (1.0f / (float)cnt) : 0.0f;
  if (j < D_HID) row[j] = g_psum[g * D_HID + j] * inv;
  __syncthreads();
  float acc = (cnt > 0) ? __ldg(&b3[j]) : 0.0f;
#pragma unroll 8
  for (int k = 0; k < D_HID; k++) acc += row[k] * __ldg(&W3[k * D_OUT + j]);
  out[(size_t)g * D_OUT + j] = acc;
}

// ---------------- launch ----------------
extern "C" void kernel_launch(void* const* d_in, const int* in_sizes, int n_in,
                              void* d_out, int out_size) {
  const float* x     = (const float*)d_in[0];
  const void*  ei    = d_in[1];
  const void*  batch = d_in[2];

  int wi = 3;
  while (wi < n_in && in_sizes[wi] <= 1) wi++;
  const float* W1 = (const float*)d_in[wi + 0];
  const float* b1 = (const float*)d_in[wi + 1];
  const float* W2 = (const float*)d_in[wi + 2];
  const float* b2 = (const float*)d_in[wi + 3];
  const float* W3 = (const float*)d_in[wi + 4];
  const float* b3 = (const float*)d_in[wi + 5];

  int N = in_sizes[2];
  int E = in_sizes[1] / 2;

  __half *bufA, *bufB;
  cudaGetSymbolAddress((void**)&bufA, g_bufA);
  cudaGetSymbolAddress((void**)&bufB, g_bufB);

  const int TB = 256;
  int nb_nodes  = (N + TB - 1) / TB;
  int nb_edges4 = ((E + 3) / 4 + TB - 1) / TB;   // 4 edges per thread
  int nb_warp   = (int)(((long long)N * 32 + TB - 1) / TB);
  int nb_mma    = (N + 255) / 256;

  int convThreads = (N * D_IN) / 4;
  int convBlocks  = (convThreads + TB - 1) / TB;

  // K0: init + detect + weight transpose (fp16)
  init_kernel<<<nb_nodes, TB>>>(ei, N, W1, W2);
  // K1: x->fp16 conversion || histogram (4 edges/thread)
  fused_convert_hist<<<convBlocks + nb_edges4, TB>>>(ei, E, x, convBlocks,
                                                     convThreads);
  // K2: rowptr scan (block 0) || all of GEMM1 (tensor cores)
  fused_scan_gemm1<<<1 + nb_mma, TB>>>(N, bufA, N);
  // K3: CSR scatter (4 edges/thread, full occupancy)
  scatter_kernel<<<nb_edges4, TB>>>(E);

  // layer 1 aggregation + gelu
  agg_gelu_kernel<<<nb_warp, TB>>>(bufA, b1, bufB, N);

  // layer 2: tensor-core GEMM 64->64, agg + gelu
  gemm2_kernel<<<nb_mma, TB>>>(bufB, bufA, N);
  agg_gelu_kernel<<<nb_warp, TB>>>(bufA, b2, bufB, N);

  // layer 3 (reordered): agg+pool in 64-dim, then [NG,64]@[64,128]+b3
  agg_pool_kernel<<<(N + 7) / 8, TB>>>(bufB, batch, N);
  final_gemm_kernel<<<out_size / D_OUT, D_OUT>>>(W3, b3, (float*)d_out);
}